// round 16
// baseline (speedup 1.0000x reference)
#include <cuda_runtime.h>
#include <cuda_fp16.h>
#include <cstddef>
#include <cstdint>

// Problem dims (fixed by the dataset)
#define INSIZE  2048
#define HSIZE   4096
#define OUTSIZE 2048

// ---------------- device scratch (no allocations allowed) ----------------
__device__ float  g_h1[HSIZE];
__device__ float  g_m1[HSIZE];
__device__ float  g_h2[HSIZE];
__device__ float  g_m2[HSIZE];
__device__ __half g_Et[(size_t)HSIZE * OUTSIZE];   // Et[n1pad][2048] fp16
__device__ __half g_A1[(size_t)HSIZE * HSIZE];     // A1T[n2p][n1p] = W2[idx2][idx1]
__device__ __half g_A2[(size_t)INSIZE * HSIZE];    // A2[2048][n1p] = W1^T[:, idx1]
__device__ __half g_B1[(size_t)HSIZE * OUTSIZE];   // B1T[2048][n2p] = W3[:, idx2]
__device__ int    g_idx1[HSIZE];
__device__ int    g_idx2[HSIZE];
__device__ int    g_cnt1[2];   // [raw, padded-to-64]
__device__ int    g_cnt2[2];
__device__ int    g_c2048[2] = {INSIZE, INSIZE};

// ---------------- fp32 GEMV, warp-per-row, 8 accumulators (MLP=16) ----------------
__global__ void gemv_kernel(const float* __restrict__ W, const float* __restrict__ v,
                            float* __restrict__ h, float* __restrict__ mask, int K)
{
    int row  = blockIdx.x * 8 + (threadIdx.x >> 5);
    int lane = threadIdx.x & 31;
    const float4* wp = (const float4*)(W + (size_t)row * K);
    const float4* vp = (const float4*)v;
    int n4 = K >> 2;                      // 512 or 1024 (multiple of 256)
    float acc[8];
    #pragma unroll
    for (int k = 0; k < 8; k++) acc[k] = 0.f;
    for (int i = lane; i < n4; i += 256) {
        #pragma unroll
        for (int k = 0; k < 8; k++) {
            float4 a = wp[i + 32 * k];
            float4 b = vp[i + 32 * k];
            acc[k] += a.x * b.x + a.y * b.y + a.z * b.z + a.w * b.w;
        }
    }
    float s = ((acc[0] + acc[1]) + (acc[2] + acc[3])) +
              ((acc[4] + acc[5]) + (acc[6] + acc[7]));
    #pragma unroll
    for (int off = 16; off > 0; off >>= 1)
        s += __shfl_xor_sync(0xffffffffu, s, off);
    if (lane == 0) {
        if (mask) {
            float m = s > 0.f ? 1.f : 0.f;
            mask[row] = m;
            h[row]    = s * m;
        } else {
            h[row] = s;
        }
    }
}

// ---------------- transpose: in[R,C] -> out[C,R] ----------------
__global__ void transpose_kernel(const float* __restrict__ in, float* __restrict__ out,
                                 int R, int C)
{
    __shared__ float tile[32][33];
    int x = blockIdx.x * 32 + threadIdx.x;
    int y = blockIdx.y * 32 + threadIdx.y;
    #pragma unroll
    for (int j = 0; j < 32; j += 8)
        tile[threadIdx.y + j][threadIdx.x] = in[(size_t)(y + j) * C + x];
    __syncthreads();
    int ox = blockIdx.y * 32 + threadIdx.x;
    int oy = blockIdx.x * 32 + threadIdx.y;
    #pragma unroll
    for (int j = 0; j < 32; j += 8)
        out[(size_t)(oy + j) * R + ox] = tile[threadIdx.x][threadIdx.y + j];
}

// ---------------- diag fill: out[N,N] = diag(d) (d==nullptr -> identity) ----------------
__global__ void diagfill_kernel(float* __restrict__ out, const float* __restrict__ d, int N)
{
    size_t idx = ((size_t)blockIdx.x * blockDim.x + threadIdx.x) * 4;
    size_t total = (size_t)N * N;
    if (idx >= total) return;
    size_t row = idx / N;
    size_t col = idx - row * N;
    float4 v = make_float4(0.f, 0.f, 0.f, 0.f);
    if (row >= col && row < col + 4) {
        float dv = d ? d[row] : 1.0f;
        ((float*)&v)[row - col] = dv;
    }
    *(float4*)(out + idx) = v;
}

// ---------------- ballot-based index build (sorted nonzero mask entries) ----------------
__global__ void build_idx_kernel(const float* __restrict__ mask, int n,
                                 int* __restrict__ idx, int* __restrict__ cnt)
{
    __shared__ int warpsum[32];
    __shared__ int sbase;
    __shared__ int stotal;
    int tid  = threadIdx.x;
    int lane = tid & 31;
    int wid  = tid >> 5;
    if (tid == 0) sbase = 0;
    __syncthreads();
    for (int chunk = 0; chunk < n; chunk += 1024) {
        int i = chunk + tid;
        int flag = (i < n && mask[i] != 0.f) ? 1 : 0;
        unsigned ball = __ballot_sync(0xffffffffu, flag);
        int wpre = __popc(ball & ((1u << lane) - 1u));
        if (lane == 0) warpsum[wid] = __popc(ball);
        __syncthreads();
        if (wid == 0) {
            int v = warpsum[lane];
            int orig = v;
            #pragma unroll
            for (int off = 1; off < 32; off <<= 1) {
                int u = __shfl_up_sync(0xffffffffu, v, off);
                if (lane >= off) v += u;
            }
            warpsum[lane] = v - orig;        // exclusive
            if (lane == 31) stotal = v;      // inclusive total
        }
        __syncthreads();
        if (flag) idx[sbase + warpsum[wid] + wpre] = i;
        __syncthreads();
        if (tid == 0) sbase += stotal;
        __syncthreads();
    }
    if (tid == 0) {
        cnt[0] = sbase;
        cnt[1] = (sbase + 63) & ~63;   // pad to 64 (BKT multiple)
    }
}

// ---------------- gather kernels -> fp16 outputs (pad exact zeros) ----------------
__global__ void gatherRC_kernel(const float* __restrict__ src, int sld,
                                const int* __restrict__ ridx, const int* __restrict__ cidx,
                                const int* __restrict__ cntr, const int* __restrict__ cntc,
                                __half* __restrict__ out)
{
    int r = blockIdx.x;
    int rc = cntr[0], rp = cntr[1];
    int cc = cntc[0], cp = cntc[1];
    if (r >= rp) return;
    bool ok = (r < rc);
    const float* s = src + (size_t)(ok ? ridx[r] : 0) * sld;
    __half* o = out + (size_t)r * cp;
    for (int j = threadIdx.x; j < cp; j += blockDim.x)
        o[j] = (ok && j < cc) ? __float2half_rn(s[cidx[j]]) : __float2half_rn(0.f);
}

__global__ void gatherC_kernel(const float* __restrict__ src, int sld,
                               const int* __restrict__ cidx, const int* __restrict__ cntc,
                               __half* __restrict__ out)
{
    int r = blockIdx.x;
    int cc = cntc[0], cp = cntc[1];
    const float* s = src + (size_t)r * sld;
    __half* o = out + (size_t)r * cp;
    for (int j = threadIdx.x; j < cp; j += blockDim.x)
        o[j] = (j < cc) ? __float2half_rn(s[cidx[j]]) : __float2half_rn(0.f);
}

// ---------------- shared GEMM config ----------------
#define BM  128
#define BN  128
#define BKT 64
#define NDIM 2048
#define ASTH 72     // NN: halves per A smem row
#define BSTH 136    // NN: halves per B smem row
#define A_HALVES (BM * ASTH)                 // 9216
#define B_HALVES (BKT * BSTH)                // 8704
#define STAGE_BYTES ((A_HALVES + B_HALVES) * 2)   // 35840
#define GEMM_DSMEM (2 * STAGE_BYTES)              // 71680
// TT: A tile [BKT][BM] stride 136, B tile [BN][BKT] stride 72
#define ATT 136
#define BTT 72
#define ATT_HALVES (BKT * ATT)               // 8704
#define BTT_HALVES (BN * BTT)                // 9216  (same stage size)

__device__ __forceinline__ void cpa16(uint32_t dst, const void* src) {
    asm volatile("cp.async.ca.shared.global [%0], [%1], 16;" :: "r"(dst), "l"(src));
}

// ---------------- NN fp16 GEMM (proven): C[M,N] = A[M,K] @ B[K,N] ----------------
template<bool HALF_OUT>
__global__ __launch_bounds__(256)
void hgemm_kernel(const int* __restrict__ kp, const int* __restrict__ mp,
                  const __half* __restrict__ A, const __half* __restrict__ B,
                  float* __restrict__ Cf, __half* __restrict__ Ch)
{
    if ((int)(blockIdx.y * BM) >= mp[1]) return;
    const int K = kp[1];
    const int nIter = K / BKT;

    extern __shared__ __half dynsm[];
    const uint32_t smBase = (uint32_t)__cvta_generic_to_shared(dynsm);

    const int tid  = threadIdx.x;
    const int wid  = tid / 32;
    const int lane = tid % 32;
    const int g    = lane >> 2;
    const int t    = lane & 3;
    const int warpM = wid % 4;
    const int warpN = wid / 4;

    const int mBase = blockIdx.y * BM;
    const int bCol  = blockIdx.x * BN;
    const size_t cBase = (size_t)mBase * NDIM + bCol;

    const int aRowInTile = ((lane >> 3) & 1) * 8 + (lane & 7);
    const int aKHalf     = (lane >> 4) * 8;
    uint32_t addrA[2];
    #pragma unroll
    for (int i = 0; i < 2; i++) {
        int row = warpM * 32 + i * 16 + aRowInTile;
        addrA[i] = smBase + (uint32_t)(row * ASTH + aKHalf) * 2;
    }
    const int bRowInTile = lane & 15;
    const int bColOff    = (lane >> 4) * 8;
    uint32_t addrB[4];
    #pragma unroll
    for (int j2 = 0; j2 < 4; j2++) {
        int col = warpN * 64 + j2 * 16 + bColOff;
        addrB[j2] = smBase + (uint32_t)(A_HALVES + bRowInTile * BSTH + col) * 2;
    }

    float acc[2][8][4];
    #pragma unroll
    for (int i = 0; i < 2; i++)
        #pragma unroll
        for (int j = 0; j < 8; j++)
            #pragma unroll
            for (int q = 0; q < 4; q++) acc[i][j][q] = 0.f;

    auto load_tile = [&](int it, int stage) {
        const int bk = it * BKT;
        const uint32_t aS = smBase + stage * STAGE_BYTES;
        const uint32_t bS = aS + A_HALVES * 2;
        #pragma unroll
        for (int p = 0; p < 4; p++) {
            int id  = tid + p * 256;
            int row = id >> 3, q = id & 7;
            cpa16(aS + (uint32_t)(row * ASTH + q * 8) * 2,
                  A + (size_t)(mBase + row) * K + bk + q * 8);
        }
        #pragma unroll
        for (int p = 0; p < 4; p++) {
            int id  = tid + p * 256;
            int row = id >> 4, c = id & 15;
            cpa16(bS + (uint32_t)(row * BSTH + c * 8) * 2,
                  B + (size_t)(bk + row) * NDIM + bCol + c * 8);
        }
        asm volatile("cp.async.commit_group;" ::: "memory");
    };

    load_tile(0, 0);

    for (int it = 0; it < nIter; it++) {
        const int cur = it & 1;
        if (it + 1 < nIter) {
            load_tile(it + 1, cur ^ 1);
            asm volatile("cp.async.wait_group 1;" ::: "memory");
        } else {
            asm volatile("cp.async.wait_group 0;" ::: "memory");
        }
        __syncthreads();

        const uint32_t so = cur * STAGE_BYTES;
        #pragma unroll
        for (int s = 0; s < 4; s++) {
            unsigned a[2][4];
            #pragma unroll
            for (int i = 0; i < 2; i++) {
                asm volatile(
                    "ldmatrix.sync.aligned.m8n8.x4.shared.b16 {%0,%1,%2,%3}, [%4];"
                    : "=r"(a[i][0]), "=r"(a[i][1]), "=r"(a[i][2]), "=r"(a[i][3])
                    : "r"(addrA[i] + so + s * 32));
            }
            unsigned b[8][2];
            #pragma unroll
            for (int j2 = 0; j2 < 4; j2++) {
                asm volatile(
                    "ldmatrix.sync.aligned.m8n8.x4.trans.shared.b16 {%0,%1,%2,%3}, [%4];"
                    : "=r"(b[2 * j2][0]), "=r"(b[2 * j2][1]),
                      "=r"(b[2 * j2 + 1][0]), "=r"(b[2 * j2 + 1][1])
                    : "r"(addrB[j2] + so + s * 16 * BSTH * 2));
            }
            #pragma unroll
            for (int i = 0; i < 2; i++)
                #pragma unroll
                for (int j = 0; j < 8; j++) {
                    asm volatile(
                        "mma.sync.aligned.m16n8k16.row.col.f32.f16.f16.f32 "
                        "{%0,%1,%2,%3}, {%4,%5,%6,%7}, {%8,%9}, {%0,%1,%2,%3};"
                        : "+f"(acc[i][j][0]), "+f"(acc[i][j][1]),
                          "+f"(acc[i][j][2]), "+f"(acc[i][j][3])
                        : "r"(a[i][0]), "r"(a[i][1]), "r"(a[i][2]), "r"(a[i][3]),
                          "r"(b[j][0]), "r"(b[j][1]));
                }
        }
        __syncthreads();
    }

    #pragma unroll
    for (int i = 0; i < 2; i++) {
        int row0 = warpM * 32 + i * 16 + g;
        #pragma unroll
        for (int j = 0; j < 8; j++) {
            int col = warpN * 64 + j * 8 + t * 2;
            if (HALF_OUT) {
                __half2 v0 = __floats2half2_rn(acc[i][j][0], acc[i][j][1]);
                __half2 v1 = __floats2half2_rn(acc[i][j][2], acc[i][j][3]);
                *(__half2*)(&Ch[cBase + (size_t)row0 * NDIM + col])       = v0;
                *(__half2*)(&Ch[cBase + (size_t)(row0 + 8) * NDIM + col]) = v1;
            } else {
                *(float2*)(&Cf[cBase + (size_t)row0 * NDIM + col]) =
                    make_float2(acc[i][j][0], acc[i][j][1]);
                *(float2*)(&Cf[cBase + (size_t)(row0 + 8) * NDIM + col]) =
                    make_float2(acc[i][j][2], acc[i][j][3]);
            }
        }
    }
}

// ---------------- TT fp16 GEMM: C[m][n] = sum_k At[k][m] * Bt[n][k] ----------------
// At: [K][M] row-major, ld = mp[1]; Bt: [2048][K] row-major, ld = kp[1].
// C = Et [.. up to mp[1] rows][2048] fp16. M-tiles beyond mp[1] exit.
__global__ __launch_bounds__(256)
void hgemm_tt(const int* __restrict__ kp, const int* __restrict__ mp,
              const __half* __restrict__ At, const __half* __restrict__ Bt,
              __half* __restrict__ Ch)
{
    if ((int)(blockIdx.y * BM) >= mp[1]) return;
    const int K   = kp[1];
    const int ldA = mp[1];
    const int nIter = K / BKT;

    extern __shared__ __half dynsm[];
    const uint32_t smBase = (uint32_t)__cvta_generic_to_shared(dynsm);
    // stage: A tile [BKT][ATT] then B tile [BN][BTT]

    const int tid  = threadIdx.x;
    const int wid  = tid / 32;
    const int lane = tid % 32;
    const int g    = lane >> 2;
    const int t    = lane & 3;
    const int warpM = wid % 4;
    const int warpN = wid / 4;

    const int mBase = blockIdx.y * BM;
    const int nBase = blockIdx.x * BN;
    const size_t cBase = (size_t)mBase * NDIM + nBase;

    // A frag (trans ldmatrix on [k][m] tile): rows k, cols m
    const int aKRow = (lane & 7) + ((lane >> 3) & 1) * 8;   // k 0..15
    const int aMOff = (lane >> 4) * 8;                       // m +0/+8
    uint32_t addrA[2];
    #pragma unroll
    for (int i = 0; i < 2; i++) {
        int mcol = warpM * 32 + i * 16 + aMOff;
        addrA[i] = smBase + (uint32_t)(aKRow * ATT + mcol) * 2;
    }
    // B frag (non-trans ldmatrix on [n][k] tile): rows n, cols k
    const int bNRow = (lane & 7) + (lane >> 4) * 8;          // n 0..15
    const int bKOff = ((lane >> 3) & 1) * 8;                 // k +0/+8
    uint32_t addrB[4];
    #pragma unroll
    for (int j2 = 0; j2 < 4; j2++) {
        int nrow = warpN * 64 + j2 * 16 + bNRow;
        addrB[j2] = smBase + (uint32_t)(ATT_HALVES + nrow * BTT + bKOff) * 2;
    }

    float acc[2][8][4];
    #pragma unroll
    for (int i = 0; i < 2; i++)
        #pragma unroll
        for (int j = 0; j < 8; j++)
            #pragma unroll
            for (int q = 0; q < 4; q++) acc[i][j][q] = 0.f;

    auto load_tile = [&](int it, int stage) {
        const int bk = it * BKT;
        const uint32_t aS = smBase + stage * STAGE_BYTES;
        const uint32_t bS = aS + ATT_HALVES * 2;
        // A tile: 64 k-rows x 16 chunks (128 m-cols)
        #pragma unroll
        for (int p = 0; p < 4; p++) {
            int id  = tid + p * 256;
            int row = id >> 4, c = id & 15;
            cpa16(aS + (uint32_t)(row * ATT + c * 8) * 2,
                  At + (size_t)(bk + row) * ldA + mBase + c * 8);
        }
        // B tile: 128 n-rows x 8 chunks (64 k-cols)
        #pragma unroll
        for (int p = 0; p < 4; p++) {
            int id  = tid + p * 256;
            int row = id >> 3, q = id & 7;
            cpa16(bS + (uint32_t)(row * BTT + q * 8) * 2,
                  Bt + (size_t)(nBase + row) * K + bk + q * 8);
        }
        asm volatile("cp.async.commit_group;" ::: "memory");
    };

    load_tile(0, 0);

    for (int it = 0; it < nIter; it++) {
        const int cur = it & 1;
        if (it + 1 < nIter) {
            load_tile(it + 1, cur ^ 1);
            asm volatile("cp.async.wait_group 1;" ::: "memory");
        } else {
            asm volatile("cp.async.wait_group 0;" ::: "memory");
        }
        __syncthreads();

        const uint32_t so = cur * STAGE_BYTES;
        #pragma unroll
        for (int s = 0; s < 4; s++) {
            unsigned a[2][4];
            #pragma unroll
            for (int i = 0; i < 2; i++) {
                unsigned r0, r1, r2, r3;
                asm volatile(
                    "ldmatrix.sync.aligned.m8n8.x4.trans.shared.b16 {%0,%1,%2,%3}, [%4];"
                    : "=r"(r0), "=r"(r1), "=r"(r2), "=r"(r3)
                    : "r"(addrA[i] + so + s * 16 * ATT * 2));
                a[i][0] = r0; a[i][2] = r1; a[i][1] = r2; a[i][3] = r3;
            }
            unsigned b[8][2];
            #pragma unroll
            for (int j2 = 0; j2 < 4; j2++) {
                asm volatile(
                    "ldmatrix.sync.aligned.m8n8.x4.shared.b16 {%0,%1,%2,%3}, [%4];"
                    : "=r"(b[2 * j2][0]), "=r"(b[2 * j2][1]),
                      "=r"(b[2 * j2 + 1][0]), "=r"(b[2 * j2 + 1][1])
                    : "r"(addrB[j2] + so + s * 32));
            }
            #pragma unroll
            for (int i = 0; i < 2; i++)
                #pragma unroll
                for (int j = 0; j < 8; j++) {
                    asm volatile(
                        "mma.sync.aligned.m16n8k16.row.col.f32.f16.f16.f32 "
                        "{%0,%1,%2,%3}, {%4,%5,%6,%7}, {%8,%9}, {%0,%1,%2,%3};"
                        : "+f"(acc[i][j][0]), "+f"(acc[i][j][1]),
                          "+f"(acc[i][j][2]), "+f"(acc[i][j][3])
                        : "r"(a[i][0]), "r"(a[i][1]), "r"(a[i][2]), "r"(a[i][3]),
                          "r"(b[j][0]), "r"(b[j][1]));
                }
        }
        __syncthreads();
    }

    #pragma unroll
    for (int i = 0; i < 2; i++) {
        int row0 = warpM * 32 + i * 16 + g;
        #pragma unroll
        for (int j = 0; j < 8; j++) {
            int col = warpN * 64 + j * 8 + t * 2;
            __half2 v0 = __floats2half2_rn(acc[i][j][0], acc[i][j][1]);
            __half2 v1 = __floats2half2_rn(acc[i][j][2], acc[i][j][3]);
            *(__half2*)(&Ch[cBase + (size_t)row0 * NDIM + col])       = v0;
            *(__half2*)(&Ch[cBase + (size_t)(row0 + 8) * NDIM + col]) = v1;
        }
    }
}

// ---------------- launch ----------------
extern "C" void kernel_launch(void* const* d_in, const int* in_sizes, int n_in,
                              void* d_out, int out_size)
{
    (void)in_sizes; (void)n_in; (void)out_size;
    const float* x  = (const float*)d_in[0];
    const float* W1 = (const float*)d_in[1];   // [4096, 2048]
    const float* W2 = (const float*)d_in[2];   // [4096, 4096]
    const float* W3 = (const float*)d_in[3];   // [2048, 4096]
    float* out = (float*)d_out;

    float *h1, *m1, *h2, *m2;
    __half *Et, *A1T, *A2, *B1T;
    int *idx1, *idx2, *cnt1, *cnt2, *c2048;
    cudaGetSymbolAddress((void**)&h1, g_h1);
    cudaGetSymbolAddress((void**)&m1, g_m1);
    cudaGetSymbolAddress((void**)&h2, g_h2);
    cudaGetSymbolAddress((void**)&m2, g_m2);
    cudaGetSymbolAddress((void**)&Et, g_Et);
    cudaGetSymbolAddress((void**)&A1T, g_A1);
    cudaGetSymbolAddress((void**)&A2, g_A2);
    cudaGetSymbolAddress((void**)&B1T, g_B1);
    cudaGetSymbolAddress((void**)&idx1, g_idx1);
    cudaGetSymbolAddress((void**)&idx2, g_idx2);
    cudaGetSymbolAddress((void**)&cnt1, g_cnt1);
    cudaGetSymbolAddress((void**)&cnt2, g_cnt2);
    cudaGetSymbolAddress((void**)&c2048, g_c2048);

    cudaFuncSetAttribute(hgemm_kernel<true>,
                         cudaFuncAttributeMaxDynamicSharedMemorySize, GEMM_DSMEM);
    cudaFuncSetAttribute(hgemm_kernel<false>,
                         cudaFuncAttributeMaxDynamicSharedMemorySize, GEMM_DSMEM);
    cudaFuncSetAttribute(hgemm_tt,
                         cudaFuncAttributeMaxDynamicSharedMemorySize, GEMM_DSMEM);

    // Output offsets (floats)
    const size_t OFF_OUT = 0;
    const size_t OFF_DJM = OFF_OUT + OUTSIZE;
    const size_t OFF_J1  = OFF_DJM + (size_t)INSIZE * OUTSIZE;
    const size_t OFF_J2  = OFF_J1  + (size_t)INSIZE * HSIZE;
    const size_t OFF_J3  = OFF_J2  + (size_t)HSIZE * HSIZE;
    const size_t OFF_J4  = OFF_J3  + (size_t)HSIZE * HSIZE;
    const size_t OFF_J5  = OFF_J4  + (size_t)HSIZE * HSIZE;
    const size_t OFF_J6  = OFF_J5  + (size_t)HSIZE * OUTSIZE;

    // ---- capture-safe fork: side streams joined before return ----
    cudaStream_t sT, sD, sG, sB;
    cudaStreamCreateWithFlags(&sT, cudaStreamNonBlocking);
    cudaStreamCreateWithFlags(&sD, cudaStreamNonBlocking);
    cudaStreamCreateWithFlags(&sG, cudaStreamNonBlocking);
    cudaStreamCreateWithFlags(&sB, cudaStreamNonBlocking);
    cudaEvent_t e0, eT1, eTall, eM1, eM2, eD, eI1, eI2, eG, eB;
    cudaEventCreateWithFlags(&e0,   cudaEventDisableTiming);
    cudaEventCreateWithFlags(&eT1,  cudaEventDisableTiming);
    cudaEventCreateWithFlags(&eTall,cudaEventDisableTiming);
    cudaEventCreateWithFlags(&eM1,  cudaEventDisableTiming);
    cudaEventCreateWithFlags(&eM2,  cudaEventDisableTiming);
    cudaEventCreateWithFlags(&eD,   cudaEventDisableTiming);
    cudaEventCreateWithFlags(&eI1,  cudaEventDisableTiming);
    cudaEventCreateWithFlags(&eI2,  cudaEventDisableTiming);
    cudaEventCreateWithFlags(&eG,   cudaEventDisableTiming);
    cudaEventCreateWithFlags(&eB,   cudaEventDisableTiming);

    cudaEventRecord(e0, 0);
    cudaStreamWaitEvent(sT, e0, 0);
    cudaStreamWaitEvent(sD, e0, 0);

    // Branch T: transposes are now pure output work (W1 first: A2 gather needs it)
    {
        dim3 blk(32, 8);
        transpose_kernel<<<dim3(INSIZE/32, HSIZE/32), blk, 0, sT>>>(W1, out + OFF_J1, HSIZE, INSIZE);
        cudaEventRecord(eT1, sT);
        transpose_kernel<<<dim3(HSIZE/32,  HSIZE/32), blk, 0, sT>>>(W2, out + OFF_J3, HSIZE, HSIZE);
        transpose_kernel<<<dim3(HSIZE/32,  OUTSIZE/32), blk, 0, sT>>>(W3, out + OFF_J5, OUTSIZE, HSIZE);
        cudaEventRecord(eTall, sT);
    }

    // Main: forward GEMV chain (fp32; warp-per-row, 8 accumulators)
    gemv_kernel<<<HSIZE / 8, 256>>>(W1, x,  h1, m1, INSIZE);
    cudaEventRecord(eM1, 0);
    gemv_kernel<<<HSIZE / 8, 256>>>(W2, h1, h2, m2, HSIZE);
    cudaEventRecord(eM2, 0);

    // Branch D: identity block early; then GEMV3 + mask diagonals
    {
        size_t nH = ((size_t)HSIZE * HSIZE) / 4;
        size_t nO = ((size_t)OUTSIZE * OUTSIZE) / 4;
        diagfill_kernel<<<(unsigned)((nO + 255) / 256), 256, 0, sD>>>(out + OFF_J6, nullptr, OUTSIZE);
        cudaStreamWaitEvent(sD, eM2, 0);
        gemv_kernel<<<OUTSIZE / 8, 256, 0, sD>>>(W3, h2, out + OFF_OUT, nullptr, HSIZE);
        diagfill_kernel<<<(unsigned)((nH + 255) / 256), 256, 0, sD>>>(out + OFF_J2, m1, HSIZE);
        diagfill_kernel<<<(unsigned)((nH + 255) / 256), 256, 0, sD>>>(out + OFF_J4, m2, HSIZE);
        cudaEventRecord(eD, sD);
    }

    // Branch G: build_idx1 overlaps GEMV2; A2 gather (needs W1^T) overlaps GEMM1
    cudaStreamWaitEvent(sG, eM1, 0);
    build_idx_kernel<<<1, 1024, 0, sG>>>(m1, HSIZE, idx1, cnt1);
    cudaEventRecord(eI1, sG);
    cudaStreamWaitEvent(sG, eT1, 0);
    gatherC_kernel<<<INSIZE, 256, 0, sG>>>(out + OFF_J1, HSIZE, idx1, cnt1, A2);
    cudaEventRecord(eG, sG);

    // Main: build_idx2; gathers read RAW INPUTS (no transpose dependency)
    build_idx_kernel<<<1, 1024>>>(m2, HSIZE, idx2, cnt2);
    cudaEventRecord(eI2, 0);
    // B1T[2048][n2p] = W3[:, idx2]  (needs idx2 only)
    cudaStreamWaitEvent(sB, eI2, 0);
    gatherC_kernel<<<OUTSIZE, 256, 0, sB>>>(W3, HSIZE, idx2, cnt2, B1T);
    cudaEventRecord(eB, sB);
    // A1T[n2p][n1p] = W2[idx2][idx1]  (needs idx1 + idx2)
    cudaStreamWaitEvent(0, eI1, 0);
    gatherRC_kernel<<<HSIZE, 256>>>(W2, HSIZE, idx2, idx1, cnt2, cnt1, A1T);

    // GEMM1 (TT): Et[m<=n1p][2048] = A1T^T @ B1T^T   (K = n2p), fp16 out
    cudaStreamWaitEvent(0, eB, 0);
    hgemm_tt<<<dim3(NDIM / BN, HSIZE / BM), 256, GEMM_DSMEM>>>(cnt2, cnt1, A1T, B1T, Et);
    // GEMM2 (NN): DJM[2048][2048] = A2 @ Et (K = n1p), fp32 out — needs A2 (eG)
    cudaStreamWaitEvent(0, eG, 0);
    hgemm_kernel<false><<<dim3(NDIM / BN, INSIZE / BM), 256, GEMM_DSMEM>>>(
        cnt1, c2048, A2, Et, out + OFF_DJM, nullptr);

    cudaStreamWaitEvent(0, eD, 0);
    cudaStreamWaitEvent(0, eTall, 0);

    cudaEventDestroy(e0); cudaEventDestroy(eT1); cudaEventDestroy(eTall);
    cudaEventDestroy(eM1); cudaEventDestroy(eM2); cudaEventDestroy(eD);
    cudaEventDestroy(eI1); cudaEventDestroy(eI2); cudaEventDestroy(eG);
    cudaEventDestroy(eB);
    cudaStreamDestroy(sT); cudaStreamDestroy(sD); cudaStreamDestroy(sG); cudaStreamDestroy(sB);
}

// round 17
// speedup vs baseline: 1.0800x; 1.0800x over previous
#include <cuda_runtime.h>
#include <cuda_fp16.h>
#include <cstddef>
#include <cstdint>

// Problem dims (fixed by the dataset)
#define INSIZE  2048
#define HSIZE   4096
#define OUTSIZE 2048

// ---------------- device scratch (no allocations allowed) ----------------
__device__ float  g_h1[HSIZE];
__device__ float  g_m1[HSIZE];
__device__ float  g_h2[HSIZE];
__device__ float  g_m2[HSIZE];
__device__ __half g_Et[(size_t)HSIZE * OUTSIZE];   // Et[n1pad][2048] fp16
__device__ __half g_A1[(size_t)HSIZE * HSIZE];     // W2^T[idx1][idx2] fp16
__device__ __half g_A2[(size_t)INSIZE * HSIZE];    // W1^T[:, idx1] fp16
__device__ __half g_B1[(size_t)HSIZE * OUTSIZE];   // W3^T rows idx2 fp16
__device__ int    g_idx1[HSIZE];
__device__ int    g_idx2[HSIZE];
__device__ int    g_cnt1[2];   // [raw, padded-to-64]
__device__ int    g_cnt2[2];
__device__ int    g_c2048[2] = {INSIZE, INSIZE};

// ---------------- fp32 GEMV, warp-per-row, 4 accumulators (R15 exact) ----------------
__global__ void gemv_kernel(const float* __restrict__ W, const float* __restrict__ v,
                            float* __restrict__ h, float* __restrict__ mask, int K)
{
    int row  = blockIdx.x * 8 + (threadIdx.x >> 5);
    int lane = threadIdx.x & 31;
    const float4* wp = (const float4*)(W + (size_t)row * K);
    const float4* vp = (const float4*)v;
    int n4 = K >> 2;
    float acc0 = 0.f, acc1 = 0.f, acc2 = 0.f, acc3 = 0.f;
    for (int i = lane; i < n4; i += 128) {
        float4 a0 = wp[i];       float4 b0 = vp[i];
        float4 a1 = wp[i + 32];  float4 b1 = vp[i + 32];
        float4 a2 = wp[i + 64];  float4 b2 = vp[i + 64];
        float4 a3 = wp[i + 96];  float4 b3 = vp[i + 96];
        acc0 += a0.x * b0.x + a0.y * b0.y + a0.z * b0.z + a0.w * b0.w;
        acc1 += a1.x * b1.x + a1.y * b1.y + a1.z * b1.z + a1.w * b1.w;
        acc2 += a2.x * b2.x + a2.y * b2.y + a2.z * b2.z + a2.w * b2.w;
        acc3 += a3.x * b3.x + a3.y * b3.y + a3.z * b3.z + a3.w * b3.w;
    }
    float acc = (acc0 + acc1) + (acc2 + acc3);
    #pragma unroll
    for (int off = 16; off > 0; off >>= 1)
        acc += __shfl_xor_sync(0xffffffffu, acc, off);
    if (lane == 0) {
        if (mask) {
            float m = acc > 0.f ? 1.f : 0.f;
            mask[row] = m;
            h[row]    = acc * m;
        } else {
            h[row] = acc;
        }
    }
}

// ---------------- float4 transpose: in[R,C] -> out[C,R], 64x64 tiles ----------------
__global__ void transpose_kernel(const float* __restrict__ in, float* __restrict__ out,
                                 int R, int C)
{
    __shared__ float tile[64][65];
    int t  = threadIdx.x;          // 0..255
    int r0 = t >> 4;               // 0..15
    int c4 = (t & 15) * 4;         // 0..60
    int bx = blockIdx.x * 64;      // col base (input)
    int by = blockIdx.y * 64;      // row base (input)
    #pragma unroll
    for (int j = 0; j < 4; j++) {
        float4 v = *(const float4*)(&in[(size_t)(by + r0 + j * 16) * C + bx + c4]);
        tile[r0 + j * 16][c4 + 0] = v.x;
        tile[r0 + j * 16][c4 + 1] = v.y;
        tile[r0 + j * 16][c4 + 2] = v.z;
        tile[r0 + j * 16][c4 + 3] = v.w;
    }
    __syncthreads();
    #pragma unroll
    for (int j = 0; j < 4; j++) {
        float4 v;
        v.x = tile[c4 + 0][r0 + j * 16];
        v.y = tile[c4 + 1][r0 + j * 16];
        v.z = tile[c4 + 2][r0 + j * 16];
        v.w = tile[c4 + 3][r0 + j * 16];
        *(float4*)(&out[(size_t)(bx + r0 + j * 16) * R + by + c4]) = v;
    }
}

// ---------------- diag fill: out[N,N] = diag(d) (d==nullptr -> identity) ----------------
__global__ void diagfill_kernel(float* __restrict__ out, const float* __restrict__ d, int N)
{
    size_t idx = ((size_t)blockIdx.x * blockDim.x + threadIdx.x) * 4;
    size_t total = (size_t)N * N;
    if (idx >= total) return;
    size_t row = idx / N;
    size_t col = idx - row * N;
    float4 v = make_float4(0.f, 0.f, 0.f, 0.f);
    if (row >= col && row < col + 4) {
        float dv = d ? d[row] : 1.0f;
        ((float*)&v)[row - col] = dv;
    }
    *(float4*)(out + idx) = v;
}

// ---------------- ballot-based index build ----------------
__global__ void build_idx_kernel(const float* __restrict__ mask, int n,
                                 int* __restrict__ idx, int* __restrict__ cnt)
{
    __shared__ int warpsum[32];
    __shared__ int sbase;
    __shared__ int stotal;
    int tid  = threadIdx.x;
    int lane = tid & 31;
    int wid  = tid >> 5;
    if (tid == 0) sbase = 0;
    __syncthreads();
    for (int chunk = 0; chunk < n; chunk += 1024) {
        int i = chunk + tid;
        int flag = (i < n && mask[i] != 0.f) ? 1 : 0;
        unsigned ball = __ballot_sync(0xffffffffu, flag);
        int wpre = __popc(ball & ((1u << lane) - 1u));
        if (lane == 0) warpsum[wid] = __popc(ball);
        __syncthreads();
        if (wid == 0) {
            int v = warpsum[lane];
            int orig = v;
            #pragma unroll
            for (int off = 1; off < 32; off <<= 1) {
                int u = __shfl_up_sync(0xffffffffu, v, off);
                if (lane >= off) v += u;
            }
            warpsum[lane] = v - orig;
            if (lane == 31) stotal = v;
        }
        __syncthreads();
        if (flag) idx[sbase + warpsum[wid] + wpre] = i;
        __syncthreads();
        if (tid == 0) sbase += stotal;
        __syncthreads();
    }
    if (tid == 0) {
        cnt[0] = sbase;
        cnt[1] = (sbase + 63) & ~63;
    }
}

// ---------------- gather kernels -> fp16 outputs (pad exact zeros) ----------------
__global__ void gatherRC_kernel(const float* __restrict__ src, int sld,
                                const int* __restrict__ ridx, const int* __restrict__ cidx,
                                const int* __restrict__ cntr, const int* __restrict__ cntc,
                                __half* __restrict__ out)
{
    int r = blockIdx.x;
    int rc = cntr[0], rp = cntr[1];
    int cc = cntc[0], cp = cntc[1];
    if (r >= rp) return;
    bool ok = (r < rc);
    const float* s = src + (size_t)(ok ? ridx[r] : 0) * sld;
    __half* o = out + (size_t)r * cp;
    for (int j = threadIdx.x; j < cp; j += blockDim.x)
        o[j] = (ok && j < cc) ? __float2half_rn(s[cidx[j]]) : __float2half_rn(0.f);
}

__global__ void gatherC_kernel(const float* __restrict__ src, int sld,
                               const int* __restrict__ cidx, const int* __restrict__ cntc,
                               __half* __restrict__ out)
{
    int r = blockIdx.x;
    int cc = cntc[0], cp = cntc[1];
    const float* s = src + (size_t)r * sld;
    __half* o = out + (size_t)r * cp;
    for (int j = threadIdx.x; j < cp; j += blockDim.x)
        o[j] = (j < cc) ? __float2half_rn(s[cidx[j]]) : __float2half_rn(0.f);
}

__global__ void gatherR_kernel(const float* __restrict__ src, int sld,
                               const int* __restrict__ ridx, const int* __restrict__ cntr,
                               __half* __restrict__ out, int ncols)
{
    int r = blockIdx.x;
    int rc = cntr[0], rp = cntr[1];
    if (r >= rp) return;
    bool ok = (r < rc);
    const float* s = src + (size_t)(ok ? ridx[r] : 0) * sld;
    __half* o = out + (size_t)r * ncols;
    for (int j = threadIdx.x * 4; j < ncols; j += blockDim.x * 4) {
        float4 v = ok ? *(const float4*)(s + j) : make_float4(0.f, 0.f, 0.f, 0.f);
        __half2 lo = __floats2half2_rn(v.x, v.y);
        __half2 hi = __floats2half2_rn(v.z, v.w);
        *(__half2*)(o + j)     = lo;
        *(__half2*)(o + j + 2) = hi;
    }
}

// ---------------- fp16 GEMM (R15 exact): m16n8k16, LDSM + cp.async, 2-stage ----------------
#define BM  128
#define BN  128
#define BKT 64
#define NDIM 2048
#define ASTH 72
#define BSTH 136
#define A_HALVES (BM * ASTH)
#define B_HALVES (BKT * BSTH)
#define STAGE_BYTES ((A_HALVES + B_HALVES) * 2)
#define GEMM_DSMEM (2 * STAGE_BYTES)

__device__ __forceinline__ void cpa16(uint32_t dst, const void* src) {
    asm volatile("cp.async.ca.shared.global [%0], [%1], 16;" :: "r"(dst), "l"(src));
}

template<bool HALF_OUT>
__global__ __launch_bounds__(256)
void hgemm_kernel(const int* __restrict__ kp, const int* __restrict__ mp,
                  const __half* __restrict__ A, const __half* __restrict__ B,
                  float* __restrict__ Cf, __half* __restrict__ Ch)
{
    if ((int)(blockIdx.y * BM) >= mp[1]) return;
    const int K = kp[1];
    const int nIter = K / BKT;

    extern __shared__ __half dynsm[];
    const uint32_t smBase = (uint32_t)__cvta_generic_to_shared(dynsm);

    const int tid  = threadIdx.x;
    const int wid  = tid / 32;
    const int lane = tid % 32;
    const int g    = lane >> 2;
    const int t    = lane & 3;
    const int warpM = wid % 4;
    const int warpN = wid / 4;

    const int mBase = blockIdx.y * BM;
    const int bCol  = blockIdx.x * BN;
    const size_t cBase = (size_t)mBase * NDIM + bCol;

    const int aRowInTile = ((lane >> 3) & 1) * 8 + (lane & 7);
    const int aKHalf     = (lane >> 4) * 8;
    uint32_t addrA[2];
    #pragma unroll
    for (int i = 0; i < 2; i++) {
        int row = warpM * 32 + i * 16 + aRowInTile;
        addrA[i] = smBase + (uint32_t)(row * ASTH + aKHalf) * 2;
    }
    const int bRowInTile = lane & 15;
    const int bColOff    = (lane >> 4) * 8;
    uint32_t addrB[4];
    #pragma unroll
    for (int j2 = 0; j2 < 4; j2++) {
        int col = warpN * 64 + j2 * 16 + bColOff;
        addrB[j2] = smBase + (uint32_t)(A_HALVES + bRowInTile * BSTH + col) * 2;
    }

    float acc[2][8][4];
    #pragma unroll
    for (int i = 0; i < 2; i++)
        #pragma unroll
        for (int j = 0; j < 8; j++)
            #pragma unroll
            for (int q = 0; q < 4; q++) acc[i][j][q] = 0.f;

    auto load_tile = [&](int it, int stage) {
        const int bk = it * BKT;
        const uint32_t aS = smBase + stage * STAGE_BYTES;
        const uint32_t bS = aS + A_HALVES * 2;
        #pragma unroll
        for (int p = 0; p < 4; p++) {
            int id  = tid + p * 256;
            int row = id >> 3, q = id & 7;
            cpa16(aS + (uint32_t)(row * ASTH + q * 8) * 2,
                  A + (size_t)(mBase + row) * K + bk + q * 8);
        }
        #pragma unroll
        for (int p = 0; p < 4; p++) {
            int id  = tid + p * 256;
            int row = id >> 4, c = id & 15;
            cpa16(bS + (uint32_t)(row * BSTH + c * 8) * 2,
                  B + (size_t)(bk + row) * NDIM + bCol + c * 8);
        }
        asm volatile("cp.async.commit_group;" ::: "memory");
    };

    load_tile(0, 0);

    for (int it = 0; it < nIter; it++) {
        const int cur = it & 1;
        if (it + 1 < nIter) {
            load_tile(it + 1, cur ^ 1);
            asm volatile("cp.async.wait_group 1;" ::: "memory");
        } else {
            asm volatile("cp.async.wait_group 0;" ::: "memory");
        }
        __syncthreads();

        const uint32_t so = cur * STAGE_BYTES;
        #pragma unroll
        for (int s = 0; s < 4; s++) {
            unsigned a[2][4];
            #pragma unroll
            for (int i = 0; i < 2; i++) {
                asm volatile(
                    "ldmatrix.sync.aligned.m8n8.x4.shared.b16 {%0,%1,%2,%3}, [%4];"
                    : "=r"(a[i][0]), "=r"(a[i][1]), "=r"(a[i][2]), "=r"(a[i][3])
                    : "r"(addrA[i] + so + s * 32));
            }
            unsigned b[8][2];
            #pragma unroll
            for (int j2 = 0; j2 < 4; j2++) {
                asm volatile(
                    "ldmatrix.sync.aligned.m8n8.x4.trans.shared.b16 {%0,%1,%2,%3}, [%4];"
                    : "=r"(b[2 * j2][0]), "=r"(b[2 * j2][1]),
                      "=r"(b[2 * j2 + 1][0]), "=r"(b[2 * j2 + 1][1])
                    : "r"(addrB[j2] + so + s * 16 * BSTH * 2));
            }
            #pragma unroll
            for (int i = 0; i < 2; i++)
                #pragma unroll
                for (int j = 0; j < 8; j++) {
                    asm volatile(
                        "mma.sync.aligned.m16n8k16.row.col.f32.f16.f16.f32 "
                        "{%0,%1,%2,%3}, {%4,%5,%6,%7}, {%8,%9}, {%0,%1,%2,%3};"
                        : "+f"(acc[i][j][0]), "+f"(acc[i][j][1]),
                          "+f"(acc[i][j][2]), "+f"(acc[i][j][3])
                        : "r"(a[i][0]), "r"(a[i][1]), "r"(a[i][2]), "r"(a[i][3]),
                          "r"(b[j][0]), "r"(b[j][1]));
                }
        }
        __syncthreads();
    }

    #pragma unroll
    for (int i = 0; i < 2; i++) {
        int row0 = warpM * 32 + i * 16 + g;
        #pragma unroll
        for (int j = 0; j < 8; j++) {
            int col = warpN * 64 + j * 8 + t * 2;
            if (HALF_OUT) {
                __half2 v0 = __floats2half2_rn(acc[i][j][0], acc[i][j][1]);
                __half2 v1 = __floats2half2_rn(acc[i][j][2], acc[i][j][3]);
                *(__half2*)(&Ch[cBase + (size_t)row0 * NDIM + col])       = v0;
                *(__half2*)(&Ch[cBase + (size_t)(row0 + 8) * NDIM + col]) = v1;
            } else {
                *(float2*)(&Cf[cBase + (size_t)row0 * NDIM + col]) =
                    make_float2(acc[i][j][0], acc[i][j][1]);
                *(float2*)(&Cf[cBase + (size_t)(row0 + 8) * NDIM + col]) =
                    make_float2(acc[i][j][2], acc[i][j][3]);
            }
        }
    }
}

// ---------------- launch ----------------
extern "C" void kernel_launch(void* const* d_in, const int* in_sizes, int n_in,
                              void* d_out, int out_size)
{
    (void)in_sizes; (void)n_in; (void)out_size;
    const float* x  = (const float*)d_in[0];
    const float* W1 = (const float*)d_in[1];   // [4096, 2048]
    const float* W2 = (const float*)d_in[2];   // [4096, 4096]
    const float* W3 = (const float*)d_in[3];   // [2048, 4096]
    float* out = (float*)d_out;

    float *h1, *m1, *h2, *m2;
    __half *Et, *A1, *A2, *B1;
    int *idx1, *idx2, *cnt1, *cnt2, *c2048;
    cudaGetSymbolAddress((void**)&h1, g_h1);
    cudaGetSymbolAddress((void**)&m1, g_m1);
    cudaGetSymbolAddress((void**)&h2, g_h2);
    cudaGetSymbolAddress((void**)&m2, g_m2);
    cudaGetSymbolAddress((void**)&Et, g_Et);
    cudaGetSymbolAddress((void**)&A1, g_A1);
    cudaGetSymbolAddress((void**)&A2, g_A2);
    cudaGetSymbolAddress((void**)&B1, g_B1);
    cudaGetSymbolAddress((void**)&idx1, g_idx1);
    cudaGetSymbolAddress((void**)&idx2, g_idx2);
    cudaGetSymbolAddress((void**)&cnt1, g_cnt1);
    cudaGetSymbolAddress((void**)&cnt2, g_cnt2);
    cudaGetSymbolAddress((void**)&c2048, g_c2048);

    cudaFuncSetAttribute(hgemm_kernel<true>,
                         cudaFuncAttributeMaxDynamicSharedMemorySize, GEMM_DSMEM);
    cudaFuncSetAttribute(hgemm_kernel<false>,
                         cudaFuncAttributeMaxDynamicSharedMemorySize, GEMM_DSMEM);

    // Output offsets (floats)
    const size_t OFF_OUT = 0;
    const size_t OFF_DJM = OFF_OUT + OUTSIZE;
    const size_t OFF_J1  = OFF_DJM + (size_t)INSIZE * OUTSIZE;
    const size_t OFF_J2  = OFF_J1  + (size_t)INSIZE * HSIZE;
    const size_t OFF_J3  = OFF_J2  + (size_t)HSIZE * HSIZE;
    const size_t OFF_J4  = OFF_J3  + (size_t)HSIZE * HSIZE;
    const size_t OFF_J5  = OFF_J4  + (size_t)HSIZE * HSIZE;
    const size_t OFF_J6  = OFF_J5  + (size_t)HSIZE * OUTSIZE;

    // ---- capture-safe fork: side streams joined before return ----
    cudaStream_t sT, sD, sG, sB;
    cudaStreamCreateWithFlags(&sT, cudaStreamNonBlocking);
    cudaStreamCreateWithFlags(&sD, cudaStreamNonBlocking);
    cudaStreamCreateWithFlags(&sG, cudaStreamNonBlocking);
    cudaStreamCreateWithFlags(&sB, cudaStreamNonBlocking);
    cudaEvent_t e0, eT2, eT3, eT1, eM1, eM2, eD, eI1, eI2, eG, eB, eK;
    cudaEventCreateWithFlags(&e0,  cudaEventDisableTiming);
    cudaEventCreateWithFlags(&eT2, cudaEventDisableTiming);
    cudaEventCreateWithFlags(&eT3, cudaEventDisableTiming);
    cudaEventCreateWithFlags(&eT1, cudaEventDisableTiming);
    cudaEventCreateWithFlags(&eM1, cudaEventDisableTiming);
    cudaEventCreateWithFlags(&eM2, cudaEventDisableTiming);
    cudaEventCreateWithFlags(&eD,  cudaEventDisableTiming);
    cudaEventCreateWithFlags(&eI1, cudaEventDisableTiming);
    cudaEventCreateWithFlags(&eI2, cudaEventDisableTiming);
    cudaEventCreateWithFlags(&eG,  cudaEventDisableTiming);
    cudaEventCreateWithFlags(&eB,  cudaEventDisableTiming);
    cudaEventCreateWithFlags(&eK,  cudaEventDisableTiming);

    cudaEventRecord(e0, 0);
    cudaStreamWaitEvent(sT, e0, 0);
    cudaStreamWaitEvent(sD, e0, 0);

    // Branch T (early, critical): W2^T then W3^T (float4 transpose, 64x64 tiles)
    {
        transpose_kernel<<<dim3(HSIZE/64,  HSIZE/64), 256, 0, sT>>>(W2, out + OFF_J3, HSIZE, HSIZE);
        cudaEventRecord(eT2, sT);    // W2^T ready (A1 gather)
        transpose_kernel<<<dim3(HSIZE/64,  OUTSIZE/64), 256, 0, sT>>>(W3, out + OFF_J5, OUTSIZE, HSIZE);
        cudaEventRecord(eT3, sT);    // W3^T ready (B1 gather)
    }

    // Main: forward GEMV chain (fp32; warp-per-row, 4 accumulators)
    gemv_kernel<<<HSIZE / 8, 256>>>(W1, x,  h1, m1, INSIZE);
    cudaEventRecord(eM1, 0);
    gemv_kernel<<<HSIZE / 8, 256>>>(W2, h1, h2, m2, HSIZE);
    cudaEventRecord(eM2, 0);

    // Branch G: build_idx1 overlaps GEMV2 (A2 gather added later, after W1^T)
    cudaStreamWaitEvent(sG, eM1, 0);
    build_idx_kernel<<<1, 1024, 0, sG>>>(m1, HSIZE, idx1, cnt1);
    cudaEventRecord(eI1, sG);

    // Main: build_idx2; B1 gather on sB, A1 gather on main
    build_idx_kernel<<<1, 1024>>>(m2, HSIZE, idx2, cnt2);
    cudaEventRecord(eI2, 0);
    cudaStreamWaitEvent(sB, eI2, 0);
    cudaStreamWaitEvent(sB, eT3, 0);
    gatherR_kernel<<<HSIZE, 256, 0, sB>>>(out + OFF_J5, OUTSIZE, idx2, cnt2, B1, OUTSIZE);
    cudaEventRecord(eB, sB);
    cudaStreamWaitEvent(0, eI1, 0);
    cudaStreamWaitEvent(0, eT2, 0);
    gatherRC_kernel<<<HSIZE, 256>>>(out + OFF_J3, HSIZE, idx1, idx2, cnt1, cnt2, A1);
    cudaEventRecord(eK, 0);   // GEMM window opens (all prefix memory work done on main)

    // Branch D (delayed under GEMM window): W1^T -> diagfills -> GEMV3 -> identity
    cudaStreamWaitEvent(sD, eK, 0);
    cudaStreamWaitEvent(sD, eM2, 0);
    {
        size_t nH = ((size_t)HSIZE * HSIZE) / 4;
        size_t nO = ((size_t)OUTSIZE * OUTSIZE) / 4;
        transpose_kernel<<<dim3(INSIZE/64, HSIZE/64), 256, 0, sD>>>(W1, out + OFF_J1, HSIZE, INSIZE);
        cudaEventRecord(eT1, sD);    // W1^T ready (A2 gather)
        diagfill_kernel<<<(unsigned)((nH + 255) / 256), 256, 0, sD>>>(out + OFF_J2, m1, HSIZE);
        diagfill_kernel<<<(unsigned)((nH + 255) / 256), 256, 0, sD>>>(out + OFF_J4, m2, HSIZE);
        gemv_kernel<<<OUTSIZE / 8, 256, 0, sD>>>(W3, h2, out + OFF_OUT, nullptr, HSIZE);
        diagfill_kernel<<<(unsigned)((nO + 255) / 256), 256, 0, sD>>>(out + OFF_J6, nullptr, OUTSIZE);
        cudaEventRecord(eD, sD);
    }

    // Branch G cont.: A2 gather (needs W1^T + idx1), overlaps GEMM1
    cudaStreamWaitEvent(sG, eT1, 0);
    gatherC_kernel<<<INSIZE, 256, 0, sG>>>(out + OFF_J1, HSIZE, idx1, cnt1, A2);
    cudaEventRecord(eG, sG);

    // GEMM1: Et[n1p, 2048] = A1 @ B1   (K = n2p, M-limit = n1p), fp16 out
    cudaStreamWaitEvent(0, eB, 0);
    hgemm_kernel<true><<<dim3(NDIM / BN, HSIZE / BM), 256, GEMM_DSMEM>>>(
        cnt2, cnt1, A1, B1, nullptr, Et);
    // GEMM2: DJM[2048, 2048] = A2 @ Et (K = n1p), fp32 out — needs A2 (eG)
    cudaStreamWaitEvent(0, eG, 0);
    hgemm_kernel<false><<<dim3(NDIM / BN, INSIZE / BM), 256, GEMM_DSMEM>>>(
        cnt1, c2048, A2, Et, out + OFF_DJM, nullptr);

    cudaStreamWaitEvent(0, eD, 0);

    cudaEventDestroy(e0); cudaEventDestroy(eT2); cudaEventDestroy(eT3);
    cudaEventDestroy(eT1); cudaEventDestroy(eM1); cudaEventDestroy(eM2);
    cudaEventDestroy(eD); cudaEventDestroy(eI1); cudaEventDestroy(eI2);
    cudaEventDestroy(eG); cudaEventDestroy(eB); cudaEventDestroy(eK);
    cudaStreamDestroy(sT); cudaStreamDestroy(sD); cudaStreamDestroy(sG); cudaStreamDestroy(sB);
}